// round 11
// baseline (speedup 1.0000x reference)
#include <cuda_runtime.h>
#include <cuda_fp16.h>
#include <cstdint>

#define BB   16
#define CC   128
#define HH   28
#define WW   28
#define FF   128
#define KK   1152      // CC*9
#define LL   784       // 28*28
#define LPAD 832       // 13*64
#define FT   64
#define LT   64
#define KC   32
#define NKC  (KK/KC)   // 36

// Scratch (allocation-free rule: __device__ globals). All values prescaled by 0.25.
__device__ __align__(16) __half g_Pneg[(size_t)BB * KK * LPAD];   // -0.25*patches (fp16), zero padded
__device__ __align__(16) __half g_Wd [(size_t)KK * 2 * FF];       // 0.25*W transposed+duplicated [K][2F]

// ---------------- im2col (negated, prescaled, fp16) + fused W-prep ----------------
// grid (13, 72+9, 16), block (16,16).
//   by < 72 : im2col as before (lp4 = bx*16+tx, k = by*16+ty)
//   by >= 72: W transpose+duplicate+prescale chunk
__global__ void __launch_bounds__(256) prep_kernel(const float* __restrict__ x,
                                                   const float* __restrict__ Wg) {
    if (blockIdx.y >= 72) {
        // ---- wtrans part: 13*9*16 = 1872 blocks x 256 thr covers 147456 elems ----
        int wb  = (blockIdx.y - 72) * 208 + blockIdx.z * 13 + blockIdx.x;  // 0..1871
        int gid = wb * 256 + threadIdx.y * 16 + threadIdx.x;
        if (gid < FF * KK) {
            int k = gid % KK, f = gid / KK;
            __half h = __float2half_rn(0.25f * Wg[f * KK + k]);
            __half2 d = __halves2half2(h, h);
            *reinterpret_cast<uint32_t*>(&g_Wd[(size_t)k * (2 * FF) + 2 * f]) =
                *reinterpret_cast<uint32_t*>(&d);
        }
        return;
    }
    const int lp4 = blockIdx.x * 16 + threadIdx.x;
    const int k   = blockIdx.y * 16 + threadIdx.y;
    const int b   = blockIdx.z;
    const int c  = k / 9;
    const int r  = k - c * 9;
    const int kh = r / 3, kw = r - kh * 3;

    const float* xp = x + ((size_t)(b * CC + c)) * (HH * WW);

    float vv[4] = {0.f, 0.f, 0.f, 0.f};
    const int l0 = lp4 * 4;
    if (l0 < LL) {
        const int oh  = lp4 / 7;
        const int ow0 = (lp4 - oh * 7) * 4;
        const int ih  = oh + kh - 1;
        if (ih >= 0 && ih < HH) {
            const float* row = xp + ih * WW;
            const int iw0 = ow0 + kw - 1;
#pragma unroll
            for (int j = 0; j < 4; j++) {
                int iw = iw0 + j;
                if (iw >= 0 && iw < WW) vv[j] = -0.25f * row[iw];
            }
        }
    }
    __half2 h0 = __floats2half2_rn(vv[0], vv[1]);
    __half2 h1 = __floats2half2_rn(vv[2], vv[3]);
    uint2 st;
    st.x = *reinterpret_cast<uint32_t*>(&h0);
    st.y = *reinterpret_cast<uint32_t*>(&h1);
    *reinterpret_cast<uint2*>(&g_Pneg[((size_t)(b * KK + k)) * LPAD + l0]) = st;
}

#define CPA16(s, g) asm volatile("cp.async.cg.shared.global [%0], [%1], 16;\n" :: "r"(s), "l"(g))

// ---------------- main L1-distance kernel (fp16, dup-W, LOP3 abs) ----------------
// 256 threads/CTA, tile 64f x 64l, per-thread 4f x 4l = 16 terms/kc.
// sWd: dup W [KC][2*FT] halves; thread tc=tid&15 -> one LDS.128 at byte 16*tc
//      yields (w0,w0)..(w3,w3). Conflict-free, zero PRMT.
// sP:  [KC][LT] halves; LDS.64 broadcast gives (p0,p1),(p2,p3).
// abs forced to LOP3 (alu pipe): bits & 0x7FFF7FFF.
// fp16 partial accumulates 2 stages (64 k, prescaled 0.25), then fp32 flush.
__global__ void __launch_bounds__(256) adder_kernel(float* __restrict__ out) {
    __shared__ __align__(16) __half2 sWd[2][KC][FT];      // 16 KB
    __shared__ __align__(16) __half2 sP [2][KC][LT / 2];  // 8 KB

    const int tid = threadIdx.x;
    const int b  = blockIdx.z;
    const int f0 = blockIdx.y * FT;
    const int l0 = blockIdx.x * LT;

    const __half* gW = g_Wd + 2 * f0;                        // [K][2F] slice
    const __half* gP = g_Pneg + (size_t)b * KK * LPAD + l0;  // [K][LPAD] slice

    const uint32_t sW_base = (uint32_t)__cvta_generic_to_shared(&sWd[0][0][0]);
    const uint32_t sP_base = (uint32_t)__cvta_generic_to_shared(&sP[0][0][0]);

    // fill: W tile/stage = 32 rows x 256B -> 2 x16B chunks/thread
    //       P tile/stage = 32 rows x 128B -> 1 x16B chunk/thread
    const int frow = tid >> 3;            // 0..31
    const int fch  = (tid & 7);           // 0..7

    auto fill = [&](int s) {
        int bufi = s & 1;
        int k0 = s * KC;
        const __half* wr = gW + (size_t)(k0 + frow) * (2 * FF);
        uint32_t wd = sW_base + (uint32_t)((bufi * KC + frow) * (FT * 4));
        CPA16(wd + (2 * fch) * 16,     wr + (2 * fch) * 8);
        CPA16(wd + (2 * fch + 1) * 16, wr + (2 * fch + 1) * 8);
        const __half* pr = gP + (size_t)(k0 + frow) * LPAD;
        uint32_t pd = sP_base + (uint32_t)((bufi * KC + frow) * (LT * 2));
        CPA16(pd + fch * 16, pr + fch * 8);
        asm volatile("cp.async.commit_group;\n" ::: "memory");
    };

    const int tc  = tid & 15;             // f = 4tc .. 4tc+3
    const int tl2 = (tid >> 4) * 2;       // half2 idx: l = 4*(tid>>4) ..+3

    __half2 hacc[4][2];                   // [fi][lpair], fp16 partial (2 stages = 64 k)
    float accf[4][4];                     // [fi][l], fp32 running
#pragma unroll
    for (int i = 0; i < 4; i++) {
        hacc[i][0] = __float2half2_rn(0.f);
        hacc[i][1] = __float2half2_rn(0.f);
#pragma unroll
        for (int j = 0; j < 4; j++) accf[i][j] = 0.f;
    }

    fill(0);
    for (int s = 0; s < NKC; s++) {
        asm volatile("cp.async.wait_group 0;\n" ::: "memory");
        __syncthreads();
        if (s + 1 < NKC) fill(s + 1);
        const int buf = s & 1;
#pragma unroll
        for (int kc = 0; kc < KC; kc++) {
            uint4 wu = *reinterpret_cast<const uint4*>(&sWd[buf][kc][4 * tc]); // 4 dup half2
            uint2 pu = *reinterpret_cast<const uint2*>(&sP[buf][kc][tl2]);     // (p0,p1),(p2,p3)
            __half2 p01 = *reinterpret_cast<__half2*>(&pu.x);
            __half2 p23 = *reinterpret_cast<__half2*>(&pu.y);
            __half2 w[4];
            w[0] = *reinterpret_cast<__half2*>(&wu.x);
            w[1] = *reinterpret_cast<__half2*>(&wu.y);
            w[2] = *reinterpret_cast<__half2*>(&wu.z);
            w[3] = *reinterpret_cast<__half2*>(&wu.w);
#pragma unroll
            for (int i = 0; i < 4; i++) {
                __half2 d0 = __hadd2(w[i], p01);   // w - p (p negated)
                __half2 d1 = __hadd2(w[i], p23);
                uint32_t a0 = *reinterpret_cast<uint32_t*>(&d0) & 0x7FFF7FFFu;  // |.| via LOP3 (alu)
                uint32_t a1 = *reinterpret_cast<uint32_t*>(&d1) & 0x7FFF7FFFu;
                hacc[i][0] = __hadd2(hacc[i][0], *reinterpret_cast<__half2*>(&a0));
                hacc[i][1] = __hadd2(hacc[i][1], *reinterpret_cast<__half2*>(&a1));
            }
        }
        // flush fp16 partials to fp32 every 2 stages (and at the end)
        if ((s & 1) == 1 || s == NKC - 1) {
#pragma unroll
            for (int i = 0; i < 4; i++) {
#pragma unroll
                for (int j = 0; j < 2; j++) {
                    float2 t = __half22float2(hacc[i][j]);
                    accf[i][2 * j]     += t.x;
                    accf[i][2 * j + 1] += t.y;
                    hacc[i][j] = __float2half2_rn(0.f);
                }
            }
        }
    }

    // epilogue: out = -4 * sum (undo 0.25 prescale)
    const int tl = (tid >> 4) * 4;
    const int lbase = l0 + tl;
    if (lbase < LL) {   // LL % 4 == 0 -> whole float4 valid or invalid
#pragma unroll
        for (int i = 0; i < 4; i++) {
            float4 v = make_float4(-4.f * accf[i][0], -4.f * accf[i][1],
                                   -4.f * accf[i][2], -4.f * accf[i][3]);
            int f = f0 + 4 * tc + i;
            *reinterpret_cast<float4*>(&out[((size_t)(b * FF + f)) * LL + lbase]) = v;
        }
    }
}

extern "C" void kernel_launch(void* const* d_in, const int* in_sizes, int n_in,
                              void* d_out, int out_size) {
    const float* x  = (const float*)d_in[0];   // [16,128,28,28]
    const float* Wg = (const float*)d_in[1];   // [128,128,3,3]
    float* out = (float*)d_out;                // [16,128,28,28]

    dim3 g1(13, 81, 16);      // 72 im2col slices + 9 wtrans slices
    dim3 b1(16, 16, 1);
    prep_kernel<<<g1, b1>>>(x, Wg);

    dim3 grid(LPAD / LT /*13*/, FF / FT /*2*/, BB /*16*/);
    adder_kernel<<<grid, 256>>>(out);
}

// round 12
// speedup vs baseline: 1.0937x; 1.0937x over previous
#include <cuda_runtime.h>
#include <cuda_fp16.h>
#include <cstdint>

#define BB   16
#define CC   128
#define HH   28
#define WW   28
#define FF   128
#define KK   1152      // CC*9
#define LL   784       // 28*28
#define LPAD 832       // 13*64
#define FT   64
#define LT   64
#define KC   32
#define NKC  (KK/KC)   // 36
#define KSPL 2
#define STG_PER (NKC / KSPL)   // 18

// Scratch (allocation-free rule: __device__ globals). Values prescaled by 0.25.
__device__ __align__(16) __half g_Pneg[(size_t)BB * KK * LPAD];     // -0.25*patches (fp16)
__device__ __align__(16) __half g_Wd [(size_t)KK * 2 * FF];         // 0.25*W transposed+duplicated [K][2F]
__device__ __align__(16) float  g_part[(size_t)KSPL * BB * FF * LL]; // k-split partials (fp32)

#define IM_BLOCKS 1664     // 16*128*208 / 256
#define W_BLOCKS  576      // 128*1152 / 256

// ---------------- prep: im2col (9 k per thread) + W transpose/dup, fused ----------------
__global__ void __launch_bounds__(256) prep_kernel(const float* __restrict__ x,
                                                   const float* __restrict__ Wg) {
    int bid = blockIdx.x;
    if (bid >= IM_BLOCKS) {
        // W transpose + duplicate + prescale
        int gid = (bid - IM_BLOCKS) * 256 + threadIdx.x;   // < 147456
        int k = gid % KK, f = gid / KK;
        __half h = __float2half_rn(0.25f * Wg[f * KK + k]);
        __half2 d = __halves2half2(h, h);
        *reinterpret_cast<uint32_t*>(&g_Wd[(size_t)k * (2 * FF) + 2 * f]) =
            *reinterpret_cast<uint32_t*>(&d);
        return;
    }
    int gid = bid * 256 + threadIdx.x;       // (b, c, lp4)
    int lp4 = gid % 208;
    int t   = gid / 208;
    int c   = t & 127;
    int b   = t >> 7;

    float xv[3][6];                          // rows oh-1..oh+1, cols ow0-1..ow0+4 (negated, prescaled)
#pragma unroll
    for (int r = 0; r < 3; r++)
#pragma unroll
        for (int j = 0; j < 6; j++) xv[r][j] = 0.f;

    const int l0 = lp4 * 4;
    if (l0 < LL) {
        const int oh  = lp4 / 7;
        const int ow0 = (lp4 - oh * 7) * 4;
        const float* xp = x + ((size_t)(b * CC + c)) * (HH * WW);
#pragma unroll
        for (int r = 0; r < 3; r++) {
            int ih = oh + r - 1;
            if (ih >= 0 && ih < HH) {
                const float* row = xp + ih * WW;
#pragma unroll
                for (int j = 0; j < 6; j++) {
                    int iw = ow0 + j - 1;
                    if (iw >= 0 && iw < WW) xv[r][j] = -0.25f * row[iw];
                }
            }
        }
    }
    __half* dst = g_Pneg + ((size_t)(b * KK + c * 9)) * LPAD + l0;
#pragma unroll
    for (int kh = 0; kh < 3; kh++)
#pragma unroll
        for (int kw = 0; kw < 3; kw++) {
            __half2 h0 = __floats2half2_rn(xv[kh][kw],     xv[kh][kw + 1]);
            __half2 h1 = __floats2half2_rn(xv[kh][kw + 2], xv[kh][kw + 3]);
            uint2 st;
            st.x = *reinterpret_cast<uint32_t*>(&h0);
            st.y = *reinterpret_cast<uint32_t*>(&h1);
            *reinterpret_cast<uint2*>(&dst[(size_t)(kh * 3 + kw) * LPAD]) = st;
        }
}

#define CPA16(s, g) asm volatile("cp.async.cg.shared.global [%0], [%1], 16;\n" :: "r"(s), "l"(g))

// ---------------- main L1-distance kernel (fp16, dup-W, habs2, k-split) ----------------
// grid (13, 4, 16): y = fhalf + 2*ksplit. 832 CTAs, 18 stages each.
__global__ void __launch_bounds__(256) adder_kernel() {
    __shared__ __align__(16) __half2 sWd[2][KC][FT];      // 16 KB
    __shared__ __align__(16) __half2 sP [2][KC][LT / 2];  // 8 KB

    const int tid = threadIdx.x;
    const int b   = blockIdx.z;
    const int fh  = blockIdx.y & 1;
    const int ks  = blockIdx.y >> 1;
    const int f0  = fh * FT;
    const int l0  = blockIdx.x * LT;
    const int s0  = ks * STG_PER;

    const __half* gW = g_Wd + 2 * f0;                        // [K][2F] slice
    const __half* gP = g_Pneg + (size_t)b * KK * LPAD + l0;  // [K][LPAD] slice

    const uint32_t sW_base = (uint32_t)__cvta_generic_to_shared(&sWd[0][0][0]);
    const uint32_t sP_base = (uint32_t)__cvta_generic_to_shared(&sP[0][0][0]);

    const int frow = tid >> 3;            // 0..31
    const int fch  = (tid & 7);           // 0..7

    auto fill = [&](int s, int bufi) {
        int k0 = s * KC;
        const __half* wr = gW + (size_t)(k0 + frow) * (2 * FF);
        uint32_t wd = sW_base + (uint32_t)((bufi * KC + frow) * (FT * 4));
        CPA16(wd + (2 * fch) * 16,     wr + (2 * fch) * 8);
        CPA16(wd + (2 * fch + 1) * 16, wr + (2 * fch + 1) * 8);
        const __half* pr = gP + (size_t)(k0 + frow) * LPAD;
        uint32_t pd = sP_base + (uint32_t)((bufi * KC + frow) * (LT * 2));
        CPA16(pd + fch * 16, pr + fch * 8);
        asm volatile("cp.async.commit_group;\n" ::: "memory");
    };

    const int tc  = tid & 15;             // f = 4tc .. 4tc+3
    const int tl2 = (tid >> 4) * 2;       // half2 idx: l = 4*(tid>>4) ..+3

    __half2 hacc[4][2];                   // [fi][lpair], fp16 partial (2 stages = 64 k)
    float accf[4][4];                     // [fi][l], fp32 running
#pragma unroll
    for (int i = 0; i < 4; i++) {
        hacc[i][0] = __float2half2_rn(0.f);
        hacc[i][1] = __float2half2_rn(0.f);
#pragma unroll
        for (int j = 0; j < 4; j++) accf[i][j] = 0.f;
    }

    fill(s0, 0);
    for (int t = 0; t < STG_PER; t++) {
        asm volatile("cp.async.wait_group 0;\n" ::: "memory");
        __syncthreads();
        if (t + 1 < STG_PER) fill(s0 + t + 1, (t + 1) & 1);
        const int buf = t & 1;
#pragma unroll
        for (int kc = 0; kc < KC; kc++) {
            uint4 wu = *reinterpret_cast<const uint4*>(&sWd[buf][kc][4 * tc]); // 4 dup half2
            uint2 pu = *reinterpret_cast<const uint2*>(&sP[buf][kc][tl2]);     // (p0,p1),(p2,p3)
            __half2 p01 = *reinterpret_cast<__half2*>(&pu.x);
            __half2 p23 = *reinterpret_cast<__half2*>(&pu.y);
            __half2 w[4];
            w[0] = *reinterpret_cast<__half2*>(&wu.x);
            w[1] = *reinterpret_cast<__half2*>(&wu.y);
            w[2] = *reinterpret_cast<__half2*>(&wu.z);
            w[3] = *reinterpret_cast<__half2*>(&wu.w);
#pragma unroll
            for (int i = 0; i < 4; i++) {
                __half2 d0 = __hadd2(w[i], p01);   // w - p (p negated)
                __half2 d1 = __hadd2(w[i], p23);
                hacc[i][0] = __hadd2(hacc[i][0], __habs2(d0));   // |.| folds into HADD2 src-mod
                hacc[i][1] = __hadd2(hacc[i][1], __habs2(d1));
            }
        }
        // flush fp16 partials to fp32 every 2 stages (and at the end)
        if ((t & 1) == 1 || t == STG_PER - 1) {
#pragma unroll
            for (int i = 0; i < 4; i++) {
#pragma unroll
                for (int j = 0; j < 2; j++) {
                    float2 tt = __half22float2(hacc[i][j]);
                    accf[i][2 * j]     += tt.x;
                    accf[i][2 * j + 1] += tt.y;
                    hacc[i][j] = __float2half2_rn(0.f);
                }
            }
        }
    }

    // store raw partial sums (reduce kernel applies -4)
    const int tl = (tid >> 4) * 4;
    const int lbase = l0 + tl;
    if (lbase < LL) {
        float* pout = g_part + (size_t)ks * (BB * FF * LL);
#pragma unroll
        for (int i = 0; i < 4; i++) {
            float4 v = make_float4(accf[i][0], accf[i][1], accf[i][2], accf[i][3]);
            int f = f0 + 4 * tc + i;
            *reinterpret_cast<float4*>(&pout[((size_t)(b * FF + f)) * LL + lbase]) = v;
        }
    }
}

// ---------------- reduce: out = -4 * (part0 + part1) ----------------
__global__ void __launch_bounds__(256) reduce_kernel(float* __restrict__ out) {
    int i = blockIdx.x * 256 + threadIdx.x;     // float4 index, < 401408
    const float4* pa = reinterpret_cast<const float4*>(g_part);
    const float4* pb = reinterpret_cast<const float4*>(g_part + (size_t)BB * FF * LL);
    float4 a = pa[i], c = pb[i];
    float4 v = make_float4(-4.f * (a.x + c.x), -4.f * (a.y + c.y),
                           -4.f * (a.z + c.z), -4.f * (a.w + c.w));
    reinterpret_cast<float4*>(out)[i] = v;
}

extern "C" void kernel_launch(void* const* d_in, const int* in_sizes, int n_in,
                              void* d_out, int out_size) {
    const float* x  = (const float*)d_in[0];   // [16,128,28,28]
    const float* Wg = (const float*)d_in[1];   // [128,128,3,3]
    float* out = (float*)d_out;                // [16,128,28,28]

    prep_kernel<<<IM_BLOCKS + W_BLOCKS, 256>>>(x, Wg);

    dim3 grid(LPAD / LT /*13*/, 2 * KSPL /*4*/, BB /*16*/);
    adder_kernel<<<grid, 256>>>();

    reduce_kernel<<<(BB * FF * LL / 4) / 256 /*1568*/, 256>>>(out);
}

// round 13
// speedup vs baseline: 1.1426x; 1.0447x over previous
#include <cuda_runtime.h>
#include <cuda_fp16.h>
#include <cstdint>

#define BB   16
#define CC   128
#define HH   28
#define WW   28
#define FF   128
#define KK   1152      // CC*9
#define LL   784       // 28*28
#define LPAD 832       // 13*64
#define FT   64
#define LT   64
#define KC   32
#define NKC  (KK/KC)   // 36
#define KSPL 4
#define STG_PER (NKC / KSPL)   // 9

// Scratch (allocation-free rule: __device__ globals). Values prescaled by 0.25.
__device__ __align__(16) __half g_Pneg[(size_t)BB * KK * LPAD];      // -0.25*patches (fp16)
__device__ __align__(16) __half g_Wd [(size_t)KK * 2 * FF];          // 0.25*W transposed+duplicated [K][2F]
__device__ __align__(16) float  g_part[(size_t)KSPL * BB * FF * LL]; // k-split partials (fp32)

#define IM_BLOCKS 1664     // 16*128*208 / 256
#define W_BLOCKS  576      // 128*1152 / 256

// ---------------- prep: im2col (9 k per thread) + W transpose/dup, fused ----------------
__global__ void __launch_bounds__(256) prep_kernel(const float* __restrict__ x,
                                                   const float* __restrict__ Wg) {
    int bid = blockIdx.x;
    if (bid >= IM_BLOCKS) {
        // W transpose + duplicate + prescale
        int gid = (bid - IM_BLOCKS) * 256 + threadIdx.x;   // < 147456
        int k = gid % KK, f = gid / KK;
        __half h = __float2half_rn(0.25f * Wg[f * KK + k]);
        __half2 d = __halves2half2(h, h);
        *reinterpret_cast<uint32_t*>(&g_Wd[(size_t)k * (2 * FF) + 2 * f]) =
            *reinterpret_cast<uint32_t*>(&d);
        return;
    }
    int gid = bid * 256 + threadIdx.x;       // (b, c, lp4)
    int lp4 = gid % 208;
    int t   = gid / 208;
    int c   = t & 127;
    int b   = t >> 7;

    float xv[3][6];                          // rows oh-1..oh+1, cols ow0-1..ow0+4 (negated, prescaled)
#pragma unroll
    for (int r = 0; r < 3; r++)
#pragma unroll
        for (int j = 0; j < 6; j++) xv[r][j] = 0.f;

    const int l0 = lp4 * 4;
    if (l0 < LL) {
        const int oh  = lp4 / 7;
        const int ow0 = (lp4 - oh * 7) * 4;
        const float* xp = x + ((size_t)(b * CC + c)) * (HH * WW);
#pragma unroll
        for (int r = 0; r < 3; r++) {
            int ih = oh + r - 1;
            if (ih >= 0 && ih < HH) {
                const float* row = xp + ih * WW;
#pragma unroll
                for (int j = 0; j < 6; j++) {
                    int iw = ow0 + j - 1;
                    if (iw >= 0 && iw < WW) xv[r][j] = -0.25f * row[iw];
                }
            }
        }
    }
    __half* dst = g_Pneg + ((size_t)(b * KK + c * 9)) * LPAD + l0;
#pragma unroll
    for (int kh = 0; kh < 3; kh++)
#pragma unroll
        for (int kw = 0; kw < 3; kw++) {
            __half2 h0 = __floats2half2_rn(xv[kh][kw],     xv[kh][kw + 1]);
            __half2 h1 = __floats2half2_rn(xv[kh][kw + 2], xv[kh][kw + 3]);
            uint2 st;
            st.x = *reinterpret_cast<uint32_t*>(&h0);
            st.y = *reinterpret_cast<uint32_t*>(&h1);
            *reinterpret_cast<uint2*>(&dst[(size_t)(kh * 3 + kw) * LPAD]) = st;
        }
}

#define CPA16(s, g) asm volatile("cp.async.cg.shared.global [%0], [%1], 16;\n" :: "r"(s), "l"(g))

// ---------------- main L1-distance kernel (fp16, dup-W, habs2, k-split x4) ----------------
// grid (13, 8, 16): y = fhalf + 2*ksplit. 1664 CTAs, 9 stages each.
__global__ void __launch_bounds__(256) adder_kernel() {
    __shared__ __align__(16) __half2 sWd[2][KC][FT];      // 16 KB
    __shared__ __align__(16) __half2 sP [2][KC][LT / 2];  // 8 KB

    const int tid = threadIdx.x;
    const int b   = blockIdx.z;
    const int fh  = blockIdx.y & 1;
    const int ks  = blockIdx.y >> 1;
    const int f0  = fh * FT;
    const int l0  = blockIdx.x * LT;
    const int s0  = ks * STG_PER;

    const __half* gW = g_Wd + 2 * f0;                        // [K][2F] slice
    const __half* gP = g_Pneg + (size_t)b * KK * LPAD + l0;  // [K][LPAD] slice

    const uint32_t sW_base = (uint32_t)__cvta_generic_to_shared(&sWd[0][0][0]);
    const uint32_t sP_base = (uint32_t)__cvta_generic_to_shared(&sP[0][0][0]);

    const int frow = tid >> 3;            // 0..31
    const int fch  = (tid & 7);           // 0..7

    auto fill = [&](int s, int bufi) {
        int k0 = s * KC;
        const __half* wr = gW + (size_t)(k0 + frow) * (2 * FF);
        uint32_t wd = sW_base + (uint32_t)((bufi * KC + frow) * (FT * 4));
        CPA16(wd + (2 * fch) * 16,     wr + (2 * fch) * 8);
        CPA16(wd + (2 * fch + 1) * 16, wr + (2 * fch + 1) * 8);
        const __half* pr = gP + (size_t)(k0 + frow) * LPAD;
        uint32_t pd = sP_base + (uint32_t)((bufi * KC + frow) * (LT * 2));
        CPA16(pd + fch * 16, pr + fch * 8);
        asm volatile("cp.async.commit_group;\n" ::: "memory");
    };

    const int tc  = tid & 15;             // f = 4tc .. 4tc+3
    const int tl2 = (tid >> 4) * 2;       // half2 idx: l = 4*(tid>>4) ..+3

    __half2 hacc[4][2];                   // [fi][lpair], fp16 partial (<=2 stages = 64 k)
    float accf[4][4];                     // [fi][l], fp32 running
#pragma unroll
    for (int i = 0; i < 4; i++) {
        hacc[i][0] = __float2half2_rn(0.f);
        hacc[i][1] = __float2half2_rn(0.f);
#pragma unroll
        for (int j = 0; j < 4; j++) accf[i][j] = 0.f;
    }

    fill(s0, 0);
    for (int t = 0; t < STG_PER; t++) {
        asm volatile("cp.async.wait_group 0;\n" ::: "memory");
        __syncthreads();
        if (t + 1 < STG_PER) fill(s0 + t + 1, (t + 1) & 1);
        const int buf = t & 1;
#pragma unroll
        for (int kc = 0; kc < KC; kc++) {
            uint4 wu = *reinterpret_cast<const uint4*>(&sWd[buf][kc][4 * tc]); // 4 dup half2
            uint2 pu = *reinterpret_cast<const uint2*>(&sP[buf][kc][tl2]);     // (p0,p1),(p2,p3)
            __half2 p01 = *reinterpret_cast<__half2*>(&pu.x);
            __half2 p23 = *reinterpret_cast<__half2*>(&pu.y);
            __half2 w[4];
            w[0] = *reinterpret_cast<__half2*>(&wu.x);
            w[1] = *reinterpret_cast<__half2*>(&wu.y);
            w[2] = *reinterpret_cast<__half2*>(&wu.z);
            w[3] = *reinterpret_cast<__half2*>(&wu.w);
#pragma unroll
            for (int i = 0; i < 4; i++) {
                __half2 d0 = __hadd2(w[i], p01);   // w - p (p negated)
                __half2 d1 = __hadd2(w[i], p23);
                hacc[i][0] = __hadd2(hacc[i][0], __habs2(d0));   // |.| folds into HADD2 src-mod
                hacc[i][1] = __hadd2(hacc[i][1], __habs2(d1));
            }
        }
        // flush fp16 partials to fp32 every 2 stages (and at the end)
        if ((t & 1) == 1 || t == STG_PER - 1) {
#pragma unroll
            for (int i = 0; i < 4; i++) {
#pragma unroll
                for (int j = 0; j < 2; j++) {
                    float2 tt = __half22float2(hacc[i][j]);
                    accf[i][2 * j]     += tt.x;
                    accf[i][2 * j + 1] += tt.y;
                    hacc[i][j] = __float2half2_rn(0.f);
                }
            }
        }
    }

    // store raw partial sums (reduce kernel applies -4)
    const int tl = (tid >> 4) * 4;
    const int lbase = l0 + tl;
    if (lbase < LL) {
        float* pout = g_part + (size_t)ks * (BB * FF * LL);
#pragma unroll
        for (int i = 0; i < 4; i++) {
            float4 v = make_float4(accf[i][0], accf[i][1], accf[i][2], accf[i][3]);
            int f = f0 + 4 * tc + i;
            *reinterpret_cast<float4*>(&pout[((size_t)(b * FF + f)) * LL + lbase]) = v;
        }
    }
}

// ---------------- reduce: out = -4 * (part0 + part1 + part2 + part3) ----------------
__global__ void __launch_bounds__(256) reduce_kernel(float* __restrict__ out) {
    int i = blockIdx.x * 256 + threadIdx.x;     // float4 index, < 401408
    const size_t STRIDE4 = (size_t)BB * FF * LL / 4;
    const float4* p0 = reinterpret_cast<const float4*>(g_part);
    float4 a = p0[i];
    float4 c = p0[i + STRIDE4];
    float4 d = p0[i + 2 * STRIDE4];
    float4 e = p0[i + 3 * STRIDE4];
    float4 v = make_float4(-4.f * (a.x + c.x + d.x + e.x),
                           -4.f * (a.y + c.y + d.y + e.y),
                           -4.f * (a.z + c.z + d.z + e.z),
                           -4.f * (a.w + c.w + d.w + e.w));
    reinterpret_cast<float4*>(out)[i] = v;
}

extern "C" void kernel_launch(void* const* d_in, const int* in_sizes, int n_in,
                              void* d_out, int out_size) {
    const float* x  = (const float*)d_in[0];   // [16,128,28,28]
    const float* Wg = (const float*)d_in[1];   // [128,128,3,3]
    float* out = (float*)d_out;                // [16,128,28,28]

    prep_kernel<<<IM_BLOCKS + W_BLOCKS, 256>>>(x, Wg);

    dim3 grid(LPAD / LT /*13*/, 2 * KSPL /*8*/, BB /*16*/);
    adder_kernel<<<grid, 256>>>();

    reduce_kernel<<<(BB * FF * LL / 4) / 256 /*1568*/, 256>>>(out);
}

// round 14
// speedup vs baseline: 1.1604x; 1.0156x over previous
#include <cuda_runtime.h>
#include <cuda_fp16.h>
#include <cstdint>

#define BB   16
#define CC   128
#define HH   28
#define WW   28
#define FF   128
#define KK   1152      // CC*9
#define LL   784       // 28*28
#define BL   (BB * LL) // 12544 = 196*64 exactly
#define NLT  196       // l-tiles of 64 over flat (b,l)
#define FT   64
#define LT   64
#define KC   32
#define NKC  (KK/KC)   // 36
#define KSPL 4
#define STG_PER (NKC / KSPL)   // 9

// Scratch (allocation-free rule: __device__ globals). Values prescaled by 0.25.
__device__ __align__(16) __half g_Pneg[(size_t)KK * BL];              // -0.25*patches (fp16), [K][B*L] flat
__device__ __align__(16) __half g_Wd [(size_t)KK * 2 * FF];           // 0.25*W transposed+duplicated [K][2F]
__device__ __align__(16) __half g_part[(size_t)KSPL * FF * BL];       // k-split partials (fp16), [ks][F][B*L]

#define IM_BLOCKS 1568     // 16*128*196 / 256
#define W_BLOCKS  576      // 128*1152 / 256

// ---------------- prep: im2col (9 k per thread, flat-BL) + W transpose/dup ----------------
__global__ void __launch_bounds__(256) prep_kernel(const float* __restrict__ x,
                                                   const float* __restrict__ Wg) {
    int bid = blockIdx.x;
    if (bid >= IM_BLOCKS) {
        // W transpose + duplicate + prescale
        int gid = (bid - IM_BLOCKS) * 256 + threadIdx.x;   // < 147456
        int k = gid % KK, f = gid / KK;
        __half h = __float2half_rn(0.25f * Wg[f * KK + k]);
        __half2 d = __halves2half2(h, h);
        *reinterpret_cast<uint32_t*>(&g_Wd[(size_t)k * (2 * FF) + 2 * f]) =
            *reinterpret_cast<uint32_t*>(&d);
        return;
    }
    int gid = bid * 256 + threadIdx.x;       // (b, c, lp4)
    int lp4 = gid % NLT;                     // 0..195, always valid (784 = 196*4)
    int t   = gid / NLT;
    int c   = t & 127;
    int b   = t >> 7;

    float xv[3][6];                          // rows oh-1..oh+1, cols ow0-1..ow0+4 (negated, prescaled)
#pragma unroll
    for (int r = 0; r < 3; r++)
#pragma unroll
        for (int j = 0; j < 6; j++) xv[r][j] = 0.f;

    const int l0  = lp4 * 4;
    const int oh  = lp4 / 7;                 // 7 float4 groups per 28-wide row
    const int ow0 = (lp4 - oh * 7) * 4;
    const float* xp = x + ((size_t)(b * CC + c)) * (HH * WW);
#pragma unroll
    for (int r = 0; r < 3; r++) {
        int ih = oh + r - 1;
        if (ih >= 0 && ih < HH) {
            const float* row = xp + ih * WW;
#pragma unroll
            for (int j = 0; j < 6; j++) {
                int iw = ow0 + j - 1;
                if (iw >= 0 && iw < WW) xv[r][j] = -0.25f * row[iw];
            }
        }
    }
    __half* dst = g_Pneg + (size_t)(c * 9) * BL + b * LL + l0;
#pragma unroll
    for (int kh = 0; kh < 3; kh++)
#pragma unroll
        for (int kw = 0; kw < 3; kw++) {
            __half2 h0 = __floats2half2_rn(xv[kh][kw],     xv[kh][kw + 1]);
            __half2 h1 = __floats2half2_rn(xv[kh][kw + 2], xv[kh][kw + 3]);
            uint2 st;
            st.x = *reinterpret_cast<uint32_t*>(&h0);
            st.y = *reinterpret_cast<uint32_t*>(&h1);
            *reinterpret_cast<uint2*>(&dst[(size_t)(kh * 3 + kw) * BL]) = st;
        }
}

#define CPA16(s, g) asm volatile("cp.async.cg.shared.global [%0], [%1], 16;\n" :: "r"(s), "l"(g))

// ---------------- main L1-distance kernel (fp16, dup-W, habs2, k-split x4, flat-BL) ----------------
// grid (196, 8): y = fhalf + 2*ksplit. 1568 CTAs, 9 stages each. Zero padding waste.
__global__ void __launch_bounds__(256) adder_kernel() {
    __shared__ __align__(16) __half2 sWd[2][KC][FT];      // 16 KB
    __shared__ __align__(16) __half2 sP [2][KC][LT / 2];  // 8 KB

    const int tid = threadIdx.x;
    const int fh  = blockIdx.y & 1;
    const int ks  = blockIdx.y >> 1;
    const int f0  = fh * FT;
    const int l0  = blockIdx.x * LT;         // flat (b,l) offset
    const int s0  = ks * STG_PER;

    const __half* gW = g_Wd + 2 * f0;        // [K][2F] slice
    const __half* gP = g_Pneg + l0;          // [K][BL] slice

    const uint32_t sW_base = (uint32_t)__cvta_generic_to_shared(&sWd[0][0][0]);
    const uint32_t sP_base = (uint32_t)__cvta_generic_to_shared(&sP[0][0][0]);

    const int frow = tid >> 3;            // 0..31
    const int fch  = (tid & 7);           // 0..7

    auto fill = [&](int s, int bufi) {
        int k0 = s * KC;
        const __half* wr = gW + (size_t)(k0 + frow) * (2 * FF);
        uint32_t wd = sW_base + (uint32_t)((bufi * KC + frow) * (FT * 4));
        CPA16(wd + (2 * fch) * 16,     wr + (2 * fch) * 8);
        CPA16(wd + (2 * fch + 1) * 16, wr + (2 * fch + 1) * 8);
        const __half* pr = gP + (size_t)(k0 + frow) * BL;
        uint32_t pd = sP_base + (uint32_t)((bufi * KC + frow) * (LT * 2));
        CPA16(pd + fch * 16, pr + fch * 8);
        asm volatile("cp.async.commit_group;\n" ::: "memory");
    };

    const int tc  = tid & 15;             // f = 4tc .. 4tc+3
    const int tl2 = (tid >> 4) * 2;       // half2 idx: l = 4*(tid>>4) ..+3

    __half2 hacc[4][2];                   // [fi][lpair], fp16 partial (<=2 stages = 64 k)
    float accf[4][4];                     // [fi][l], fp32 running
#pragma unroll
    for (int i = 0; i < 4; i++) {
        hacc[i][0] = __float2half2_rn(0.f);
        hacc[i][1] = __float2half2_rn(0.f);
#pragma unroll
        for (int j = 0; j < 4; j++) accf[i][j] = 0.f;
    }

    fill(s0, 0);
    for (int t = 0; t < STG_PER; t++) {
        asm volatile("cp.async.wait_group 0;\n" ::: "memory");
        __syncthreads();
        if (t + 1 < STG_PER) fill(s0 + t + 1, (t + 1) & 1);
        const int buf = t & 1;
#pragma unroll
        for (int kc = 0; kc < KC; kc++) {
            uint4 wu = *reinterpret_cast<const uint4*>(&sWd[buf][kc][4 * tc]); // 4 dup half2
            uint2 pu = *reinterpret_cast<const uint2*>(&sP[buf][kc][tl2]);     // (p0,p1),(p2,p3)
            __half2 p01 = *reinterpret_cast<__half2*>(&pu.x);
            __half2 p23 = *reinterpret_cast<__half2*>(&pu.y);
            __half2 w[4];
            w[0] = *reinterpret_cast<__half2*>(&wu.x);
            w[1] = *reinterpret_cast<__half2*>(&wu.y);
            w[2] = *reinterpret_cast<__half2*>(&wu.z);
            w[3] = *reinterpret_cast<__half2*>(&wu.w);
#pragma unroll
            for (int i = 0; i < 4; i++) {
                __half2 d0 = __hadd2(w[i], p01);   // w - p (p negated)
                __half2 d1 = __hadd2(w[i], p23);
                hacc[i][0] = __hadd2(hacc[i][0], __habs2(d0));   // |.| folds into HADD2 src-mod
                hacc[i][1] = __hadd2(hacc[i][1], __habs2(d1));
            }
        }
        // flush fp16 partials to fp32 every 2 stages (and at the end)
        if ((t & 1) == 1 || t == STG_PER - 1) {
#pragma unroll
            for (int i = 0; i < 4; i++) {
#pragma unroll
                for (int j = 0; j < 2; j++) {
                    float2 tt = __half22float2(hacc[i][j]);
                    accf[i][2 * j]     += tt.x;
                    accf[i][2 * j + 1] += tt.y;
                    hacc[i][j] = __float2half2_rn(0.f);
                }
            }
        }
    }

    // store fp16 partial sums [ks][F][BL]
    const int lflat = l0 + (tid >> 4) * 4;
    __half* pout = g_part + (size_t)ks * (FF * BL);
#pragma unroll
    for (int i = 0; i < 4; i++) {
        __half2 h0 = __floats2half2_rn(accf[i][0], accf[i][1]);
        __half2 h1 = __floats2half2_rn(accf[i][2], accf[i][3]);
        uint2 st;
        st.x = *reinterpret_cast<uint32_t*>(&h0);
        st.y = *reinterpret_cast<uint32_t*>(&h1);
        int f = f0 + 4 * tc + i;
        *reinterpret_cast<uint2*>(&pout[(size_t)f * BL + lflat]) = st;
    }
}

// ---------------- reduce: out[b][f][l] = -4 * sum_ks part[ks][f][b*784+l] ----------------
__global__ void __launch_bounds__(256) reduce_kernel(float* __restrict__ out) {
    int i = blockIdx.x * 256 + threadIdx.x;     // out float4 index, < 401408
    int o = i * 4;
    int b = o / (FF * LL);
    int rem = o - b * (FF * LL);
    int f = rem / LL;
    int l = rem - f * LL;
    size_t p = (size_t)f * BL + b * LL + l;     // halves, 4-aligned

    float s[4] = {0.f, 0.f, 0.f, 0.f};
#pragma unroll
    for (int ks = 0; ks < KSPL; ks++) {
        uint2 u = *reinterpret_cast<const uint2*>(&g_part[(size_t)ks * (FF * BL) + p]);
        __half2 h0 = *reinterpret_cast<__half2*>(&u.x);
        __half2 h1 = *reinterpret_cast<__half2*>(&u.y);
        float2 a = __half22float2(h0);
        float2 c = __half22float2(h1);
        s[0] += a.x; s[1] += a.y; s[2] += c.x; s[3] += c.y;
    }
    float4 v = make_float4(-4.f * s[0], -4.f * s[1], -4.f * s[2], -4.f * s[3]);
    reinterpret_cast<float4*>(out)[i] = v;
}

extern "C" void kernel_launch(void* const* d_in, const int* in_sizes, int n_in,
                              void* d_out, int out_size) {
    const float* x  = (const float*)d_in[0];   // [16,128,28,28]
    const float* Wg = (const float*)d_in[1];   // [128,128,3,3]
    float* out = (float*)d_out;                // [16,128,28,28]

    prep_kernel<<<IM_BLOCKS + W_BLOCKS, 256>>>(x, Wg);

    dim3 grid(NLT /*196*/, 2 * KSPL /*8*/, 1);
    adder_kernel<<<grid, 256>>>();

    reduce_kernel<<<(BB * FF * LL / 4) / 256 /*1568*/, 256>>>(out);
}